// round 6
// baseline (speedup 1.0000x reference)
#include <cuda_runtime.h>
#include <cfloat>
#include <cstdint>

// Problem constants (fixed by the dataset)
#define N_B 16
#define D   128
#define H   384
#define L_0 2048
#define L_1 1024
#define S_0 32      // L0 split count for partial reduction
#define S_1 16      // L1 split count
#define LC  64      // rows per reduction block

#define TM  64      // GEMM tile rows
#define KC  16      // GEMM K chunk (double-buffered smem fits 48KB)

#define GEMM_BLKS_0 (N_B * (L_0 / TM))   // 512
#define GEMM_BLKS_1 (N_B * (L_1 / TM))   // 256
#define RED_BLKS_0  (N_B * S_0)          // 512
#define RED_BLKS_1  (N_B * S_1)          // 256

// ---------------- scratch (static device arrays; no allocation) ----------------
__device__ float g_pm1_0[N_B * S_0 * D];
__device__ float g_pm2_0[N_B * S_0 * D];
__device__ int   g_pix_0[N_B * S_0 * D];
__device__ float g_pm1_1[N_B * S_1 * D];
__device__ float g_pm2_1[N_B * S_1 * D];
__device__ int   g_pix_1[N_B * S_1 * D];

__device__ float g_c0[N_B * D];   __device__ int g_am0[N_B * D];
__device__ float g_c1[N_B * D];   __device__ int g_am1[N_B * D];
__device__ float g_base0[N_B * D];
__device__ float g_base1[N_B * D];

// ---------------- packed f32x2 helpers (sm_103a) ----------------
__device__ __forceinline__ unsigned long long packdup(float a) {
    unsigned int u = __float_as_uint(a);
    unsigned long long r;
    asm("mov.b64 %0, {%1, %1};" : "=l"(r) : "r"(u));
    return r;
}
__device__ __forceinline__ void fma2(unsigned long long& d,
                                     unsigned long long a,
                                     unsigned long long b) {
    asm("fma.rn.f32x2 %0, %1, %2, %0;" : "+l"(d) : "l"(a), "l"(b));
}
__device__ __forceinline__ void unpack2(unsigned long long v, float& lo, float& hi) {
    unsigned int a, b;
    asm("mov.b64 {%0, %1}, %2;" : "=r"(a), "=r"(b) : "l"(v));
    lo = __uint_as_float(a);
    hi = __uint_as_float(b);
}

// ---------------- K1: partial top-2 (+argmax), both groups in ONE launch ------
// grid RED_BLKS_0 + RED_BLKS_1, block 128 (one thread per d). Coalesced streams.
__global__ void k_reduce_all(const float* __restrict__ x0,
                             const float* __restrict__ x1) {
    int bid = blockIdx.x;
    const float* x;
    int S, n, s, L;
    float *pm1, *pm2; int *pix;
    if (bid < RED_BLKS_0) {
        x = x0; S = S_0; L = L_0;
        n = bid / S_0; s = bid % S_0;
        pm1 = g_pm1_0; pm2 = g_pm2_0; pix = g_pix_0;
    } else {
        bid -= RED_BLKS_0;
        x = x1; S = S_1; L = L_1;
        n = bid / S_1; s = bid % S_1;
        pm1 = g_pm1_1; pm2 = g_pm2_1; pix = g_pix_1;
    }
    int d = threadIdx.x;
    const float* p = x + ((size_t)n * L + (size_t)s * LC) * D + d;

    float m1 = -FLT_MAX, m2 = -FLT_MAX;
    int idx = 0;
#pragma unroll 4
    for (int l = 0; l < LC; l++) {
        float v = p[(size_t)l * D];
        if (v > m1) { m2 = m1; m1 = v; idx = s * LC + l; }
        else if (v > m2) { m2 = v; }
    }
    int o = (n * S + s) * D + d;
    pm1[o] = m1; pm2[o] = m2; pix[o] = idx;
}

// ---------------- K2: combine partials + compute base vectors ----------------
// grid N, block 256. Threads 0..127 handle group 0 d's, 128..255 group 1 d's.
// Merge is exact: a partial's m2 <= its m1, so on the non-promote path only the
// partial's m1 can become the global second max.
__global__ void k_combine(const float* __restrict__ W0, const float* __restrict__ b0,
                          const float* __restrict__ W1, const float* __restrict__ b1) {
    __shared__ float sm0[D];   // m1 of x0 per d
    __shared__ float sm1[D];   // m1 of x1 per d
    int n = blockIdx.x;
    int t = threadIdx.x;

    if (t < D) {
        int d = t;
        float m1 = -FLT_MAX, m2 = -FLT_MAX; int idx = 0;
        for (int s = 0; s < S_0; s++) {
            int o = (n * S_0 + s) * D + d;
            float a = g_pm1_0[o], bb = g_pm2_0[o];
            if (a > m1) { m2 = fmaxf(m1, bb); m1 = a; idx = g_pix_0[o]; }
            else        { m2 = fmaxf(m2, a); }
        }
        sm0[d] = m1;
        g_c0[n * D + d] = m2 - m1;   // <= 0; 0 on duplicate-max (exact)
        g_am0[n * D + d] = idx;
    } else {
        int d = t - D;
        float m1 = -FLT_MAX, m2 = -FLT_MAX; int idx = 0;
        for (int s = 0; s < S_1; s++) {
            int o = (n * S_1 + s) * D + d;
            float a = g_pm1_1[o], bb = g_pm2_1[o];
            if (a > m1) { m2 = fmaxf(m1, bb); m1 = a; idx = g_pix_1[o]; }
            else        { m2 = fmaxf(m2, a); }
        }
        sm1[d] = m1;
        g_c1[n * D + d] = m2 - m1;
        g_am1[n * D + d] = idx;
    }
    __syncthreads();

    // base_g[n,o] = b_g[o] + sum_d m1_x0 * W_g[o,128+d] + sum_d m1_x1 * W_g[o,256+d]
    // 4 independent accumulators + unroll 8 -> MLP ~16 on the strided W loads.
    if (t < D) {
        int o = t;
        const float* w = W0 + (size_t)o * H;
        float a0 = b0[o], a1 = 0.f, a2 = 0.f, a3 = 0.f;
#pragma unroll 8
        for (int d = 0; d < D; d += 2) {
            a0 += sm0[d]     * w[128 + d];
            a1 += sm1[d]     * w[256 + d];
            a2 += sm0[d + 1] * w[129 + d];
            a3 += sm1[d + 1] * w[257 + d];
        }
        g_base0[n * D + o] = (a0 + a1) + (a2 + a3);
    } else {
        int o = t - D;
        const float* w = W1 + (size_t)o * H;
        float a0 = b1[o], a1 = 0.f, a2 = 0.f, a3 = 0.f;
#pragma unroll 8
        for (int d = 0; d < D; d += 2) {
            a0 += sm0[d]     * w[128 + d];
            a1 += sm1[d]     * w[256 + d];
            a2 += sm0[d + 1] * w[129 + d];
            a3 += sm1[d + 1] * w[257 + d];
        }
        g_base1[n * D + o] = (a0 + a1) + (a2 + a3);
    }
}

// ---------------- K3: both GEMMs in ONE launch -------------------------------
// y = x @ Wa^T + base + sparse LOO corrections.
// Block: 256 threads, tile TM=64 rows x 128 cols, K=128 in 8 chunks of 16,
// double-buffered smem with register staging (one __syncthreads per chunk).
// Thread (tx,ty): 8 rows (ty*8..+7) x 4 cols (tx*4..+3), packed f32x2 row-pairs.
__global__ void __launch_bounds__(256) k_gemm_all(
        const float* __restrict__ x0, const float* __restrict__ W0,
        const float* __restrict__ x1, const float* __restrict__ W1,
        float* __restrict__ y0, float* __restrict__ y1) {
    __shared__ __align__(16) float xs[2][KC][TM + 4];   // 2*16*68*4  = 8704 B
    __shared__ __align__(16) float ws[2][KC][D + 4];    // 2*16*132*4 = 16896 B
    __shared__ __align__(16) float sB[D];
    __shared__ float sC[D];
    __shared__ int   sAm[D];

    // ---- group select (block-uniform) ----
    const float *x, *W; float* y;
    const float* gC; const float* gB; const int* gAm;
    int L, OFF, n, l0;
    if (blockIdx.x < GEMM_BLKS_0) {
        x = x0; W = W0; y = y0; L = L_0; OFF = 128;
        gC = g_c0; gB = g_base0; gAm = g_am0;
        n  = blockIdx.x / (L_0 / TM);
        l0 = (blockIdx.x % (L_0 / TM)) * TM;
    } else {
        int bid = blockIdx.x - GEMM_BLKS_0;
        x = x1; W = W1; y = y1; L = L_1; OFF = 256;
        gC = g_c1; gB = g_base1; gAm = g_am1;
        n  = bid / (L_1 / TM);
        l0 = (bid % (L_1 / TM)) * TM;
    }
    const float* xblk = x + ((size_t)n * L + l0) * D;

    const int t  = threadIdx.x;
    const int tx = t & 31;    // col quad
    const int ty = t >> 5;    // row octet (== warp id)

    if (t < D) {
        sC[t] = gC[n * D + t]; sAm[t] = gAm[n * D + t]; sB[t] = gB[n * D + t];
    }

    // staging registers: 1 float4 of x, 2 float4 of W per thread per chunk
    const int xrow = t >> 2, xcq = t & 3;           // 64 rows x 4 col-quads
    const int wo0 = t >> 2,        wkq0 = t & 3;    // first 256 float4s of W chunk
    const int wo1 = (t + 256) >> 2, wkq1 = t & 3;   // second 256

    float4 xr, wr0, wr1;
    auto ldR = [&](int kc) {
        xr  = *(const float4*)(xblk + (size_t)xrow * D + kc + xcq * 4);
        wr0 = *(const float4*)(W + (size_t)wo0 * H + kc + wkq0 * 4);
        wr1 = *(const float4*)(W + (size_t)wo1 * H + kc + wkq1 * 4);
    };
    auto stS = [&](int b) {
        xs[b][xcq * 4 + 0][xrow] = xr.x; xs[b][xcq * 4 + 1][xrow] = xr.y;
        xs[b][xcq * 4 + 2][xrow] = xr.z; xs[b][xcq * 4 + 3][xrow] = xr.w;
        ws[b][wkq0 * 4 + 0][wo0] = wr0.x; ws[b][wkq0 * 4 + 1][wo0] = wr0.y;
        ws[b][wkq0 * 4 + 2][wo0] = wr0.z; ws[b][wkq0 * 4 + 3][wo0] = wr0.w;
        ws[b][wkq1 * 4 + 0][wo1] = wr1.x; ws[b][wkq1 * 4 + 1][wo1] = wr1.y;
        ws[b][wkq1 * 4 + 2][wo1] = wr1.z; ws[b][wkq1 * 4 + 3][wo1] = wr1.w;
    };

    unsigned long long acc[4][4];
#pragma unroll
    for (int p = 0; p < 4; p++)
#pragma unroll
        for (int c = 0; c < 4; c++) acc[p][c] = 0ULL;

    // pipeline prologue
    ldR(0);
    stS(0);
    __syncthreads();

    const int NCH = D / KC;   // 8
#pragma unroll 1
    for (int i = 0; i < NCH; i++) {
        const int b = i & 1;
        if (i + 1 < NCH) ldR((i + 1) * KC);   // LDG overlapped with compute below

#pragma unroll
        for (int k = 0; k < KC; k++) {
            const ulonglong2 xA = *(const ulonglong2*)&xs[b][k][ty * 8];
            const ulonglong2 xB = *(const ulonglong2*)&xs[b][k][ty * 8 + 4];
            const float4 wv = *(const float4*)&ws[b][k][tx * 4];
            const unsigned long long w0 = packdup(wv.x), w1 = packdup(wv.y);
            const unsigned long long w2 = packdup(wv.z), w3 = packdup(wv.w);
            fma2(acc[0][0], xA.x, w0); fma2(acc[0][1], xA.x, w1);
            fma2(acc[0][2], xA.x, w2); fma2(acc[0][3], xA.x, w3);
            fma2(acc[1][0], xA.y, w0); fma2(acc[1][1], xA.y, w1);
            fma2(acc[1][2], xA.y, w2); fma2(acc[1][3], xA.y, w3);
            fma2(acc[2][0], xB.x, w0); fma2(acc[2][1], xB.x, w1);
            fma2(acc[2][2], xB.x, w2); fma2(acc[2][3], xB.x, w3);
            fma2(acc[3][0], xB.y, w0); fma2(acc[3][1], xB.y, w1);
            fma2(acc[3][2], xB.y, w2); fma2(acc[3][3], xB.y, w3);
        }

        if (i + 1 < NCH) {
            stS(b ^ 1);        // safe: all warps finished reading b^1 at previous sync
            __syncthreads();   // next chunk visible; also guards buffer reuse
        }
    }
    __syncthreads();           // sB/sC/sAm visible for epilogue (and final chunk done)

    // epilogue: unpack, sparse LOO corrections (in registers, deterministic), base, store
    float out[8][4];
#pragma unroll
    for (int p = 0; p < 4; p++)
#pragma unroll
        for (int c = 0; c < 4; c++) unpack2(acc[p][c], out[2 * p][c], out[2 * p + 1][c]);

    const float* Wc = W + OFF;
#pragma unroll 1
    for (int d = 0; d < D; d++) {
        int r = sAm[d] - l0;
        if ((unsigned)r < (unsigned)TM && (r >> 3) == ty) {   // uniform per warp (warp == ty)
            float coeff = sC[d];
            int rr = r & 7;
#pragma unroll
            for (int j = 0; j < 4; j++)
                out[rr][j] += coeff * Wc[(size_t)(tx * 4 + j) * H + d];
        }
    }

    const float4 bv = *(const float4*)&sB[tx * 4];
    float* yb = y + ((size_t)n * L + l0) * D + tx * 4;
#pragma unroll
    for (int r = 0; r < 8; r++) {
        float4 o4;
        o4.x = out[r][0] + bv.x; o4.y = out[r][1] + bv.y;
        o4.z = out[r][2] + bv.z; o4.w = out[r][3] + bv.w;
        *(float4*)(yb + (size_t)(ty * 8 + r) * D) = o4;
    }
}

// ---------------- launch ----------------
extern "C" void kernel_launch(void* const* d_in, const int* in_sizes, int n_in,
                              void* d_out, int out_size) {
    const float* x0 = (const float*)d_in[0];
    const float* x1 = (const float*)d_in[1];
    const float* W0 = (const float*)d_in[2];
    const float* b0 = (const float*)d_in[3];
    const float* W1 = (const float*)d_in[4];
    const float* b1 = (const float*)d_in[5];
    float* y0 = (float*)d_out;
    // y0 has exactly in_sizes[0] elements (D_in == D_out == 128)
    float* y1 = y0 + (size_t)in_sizes[0];

    k_reduce_all<<<RED_BLKS_0 + RED_BLKS_1, 128>>>(x0, x1);
    k_combine<<<N_B, 256>>>(W0, b0, W1, b1);
    k_gemm_all<<<GEMM_BLKS_0 + GEMM_BLKS_1, 256>>>(x0, W0, x1, W1, y0, y1);
}

// round 14
// speedup vs baseline: 1.2383x; 1.2383x over previous
#include <cuda_runtime.h>
#include <cfloat>
#include <cstdint>

// Problem constants (fixed by the dataset)
#define N_B 16
#define D   128
#define H   384
#define L_0 2048
#define L_1 1024
#define S_0 32      // L0 split count for partial reduction
#define S_1 16      // L1 split count
#define LC  64      // rows per reduction block

#define TM  64      // GEMM tile rows
#define KC  16      // GEMM K chunk (double-buffered smem fits 48KB)

#define GEMM_BLKS_0 (N_B * (L_0 / TM))   // 512
#define GEMM_BLKS_1 (N_B * (L_1 / TM))   // 256
#define RED_BLKS_0  (N_B * S_0)          // 512
#define RED_BLKS_1  (N_B * S_1)          // 256

// ---------------- scratch (static device arrays; no allocation) ----------------
__device__ float g_pm1_0[N_B * S_0 * D];
__device__ float g_pm2_0[N_B * S_0 * D];
__device__ int   g_pix_0[N_B * S_0 * D];
__device__ float g_pm1_1[N_B * S_1 * D];
__device__ float g_pm2_1[N_B * S_1 * D];
__device__ int   g_pix_1[N_B * S_1 * D];

__device__ float g_c0[N_B * D];   __device__ int g_am0[N_B * D];
__device__ float g_c1[N_B * D];   __device__ int g_am1[N_B * D];
__device__ float g_base0[N_B * D];
__device__ float g_base1[N_B * D];

// ---------------- packed f32x2 helpers (sm_103a) ----------------
__device__ __forceinline__ unsigned long long packdup(float a) {
    unsigned int u = __float_as_uint(a);
    unsigned long long r;
    asm("mov.b64 %0, {%1, %1};" : "=l"(r) : "r"(u));
    return r;
}
__device__ __forceinline__ void fma2(unsigned long long& d,
                                     unsigned long long a,
                                     unsigned long long b) {
    asm("fma.rn.f32x2 %0, %1, %2, %0;" : "+l"(d) : "l"(a), "l"(b));
}
__device__ __forceinline__ void unpack2(unsigned long long v, float& lo, float& hi) {
    unsigned int a, b;
    asm("mov.b64 {%0, %1}, %2;" : "=r"(a), "=r"(b) : "l"(v));
    lo = __uint_as_float(a);
    hi = __uint_as_float(b);
}

// branchless top-2 + argmax step. Exact on ties: v==m1 -> m2 becomes m1's value
// (duplicate max), and the LOO correction coefficient m2-m1 is then 0.
__device__ __forceinline__ void upd2(float v, int row, float& m1, float& m2, int& idx) {
    bool gt = v > m1;                    // strict: keeps first occurrence
    m2 = fmaxf(m2, fminf(m1, v));        // = old m1 if promoted, else candidate v
    m1 = gt ? v : m1;
    idx = gt ? row : idx;
}

// ---------------- K1: partial top-2 (+argmax), both groups in ONE launch ------
// grid RED_BLKS_0 + RED_BLKS_1, block 128. Warp w handles 16 rows of the 64-row
// chunk; each lane owns 4 columns via float4 loads (coalesced 512B per row).
// Branchless FMNMX chains, 4 independent lanes per thread. smem merge across warps.
__global__ void __launch_bounds__(128) k_reduce_all(const float* __restrict__ x0,
                                                    const float* __restrict__ x1) {
    int bid = blockIdx.x;
    const float* x;
    int S, n, s, L;
    float *pm1, *pm2; int *pix;
    if (bid < RED_BLKS_0) {
        x = x0; S = S_0; L = L_0;
        n = bid / S_0; s = bid % S_0;
        pm1 = g_pm1_0; pm2 = g_pm2_0; pix = g_pix_0;
    } else {
        bid -= RED_BLKS_0;
        x = x1; S = S_1; L = L_1;
        n = bid / S_1; s = bid % S_1;
        pm1 = g_pm1_1; pm2 = g_pm2_1; pix = g_pix_1;
    }
    const int w    = threadIdx.x >> 5;   // warp 0..3 -> rows w*16..w*16+15
    const int lane = threadIdx.x & 31;   // cols lane*4..lane*4+3

    const float4* p = (const float4*)(x + ((size_t)n * L + (size_t)s * LC + w * 16) * D) + lane;
    const int rowbase = s * LC + w * 16;

    float4 m1 = make_float4(-FLT_MAX, -FLT_MAX, -FLT_MAX, -FLT_MAX);
    float4 m2 = m1;
    int4 idx = make_int4(0, 0, 0, 0);
#pragma unroll
    for (int i = 0; i < 16; i++) {
        float4 v = p[(size_t)i * (D / 4)];
        int r = rowbase + i;
        upd2(v.x, r, m1.x, m2.x, idx.x);
        upd2(v.y, r, m1.y, m2.y, idx.y);
        upd2(v.z, r, m1.z, m2.z, idx.z);
        upd2(v.w, r, m1.w, m2.w, idx.w);
    }

    __shared__ float s1[4][D], s2[4][D];
    __shared__ int   si[4][D];
    int c = lane * 4;
    s1[w][c] = m1.x; s1[w][c + 1] = m1.y; s1[w][c + 2] = m1.z; s1[w][c + 3] = m1.w;
    s2[w][c] = m2.x; s2[w][c + 1] = m2.y; s2[w][c + 2] = m2.z; s2[w][c + 3] = m2.w;
    si[w][c] = idx.x; si[w][c + 1] = idx.y; si[w][c + 2] = idx.z; si[w][c + 3] = idx.w;
    __syncthreads();

    // thread t merges column t across the 4 warps (ascending row order)
    int t = threadIdx.x;
    float M1 = s1[0][t], M2 = s2[0][t]; int I = si[0][t];
#pragma unroll
    for (int ww = 1; ww < 4; ww++) {
        float a = s1[ww][t], b2 = s2[ww][t];
        if (a > M1) { M2 = fmaxf(M1, b2); M1 = a; I = si[ww][t]; }
        else        { M2 = fmaxf(M2, a); }   // a is this warp's max; its m2 <= a
    }
    int o = (n * S + s) * D + t;
    pm1[o] = M1; pm2[o] = M2; pix[o] = I;
}

// ---------------- K2: combine partials + compute base vectors ----------------
// grid N, block 256. Threads 0..127 handle group 0 d's, 128..255 group 1 d's.
// Merge is exact: a partial's m2 <= its m1, so on the non-promote path only the
// partial's m1 can become the global second max.
__global__ void k_combine(const float* __restrict__ W0, const float* __restrict__ b0,
                          const float* __restrict__ W1, const float* __restrict__ b1) {
    __shared__ __align__(16) float sm0[D];   // m1 of x0 per d
    __shared__ __align__(16) float sm1[D];   // m1 of x1 per d
    int n = blockIdx.x;
    int t = threadIdx.x;

    if (t < D) {
        int d = t;
        float m1 = -FLT_MAX, m2 = -FLT_MAX; int idx = 0;
        for (int s = 0; s < S_0; s++) {
            int o = (n * S_0 + s) * D + d;
            float a = g_pm1_0[o], bb = g_pm2_0[o];
            if (a > m1) { m2 = fmaxf(m1, bb); m1 = a; idx = g_pix_0[o]; }
            else        { m2 = fmaxf(m2, a); }
        }
        sm0[d] = m1;
        g_c0[n * D + d] = m2 - m1;   // <= 0; 0 on duplicate-max (exact)
        g_am0[n * D + d] = idx;
    } else {
        int d = t - D;
        float m1 = -FLT_MAX, m2 = -FLT_MAX; int idx = 0;
        for (int s = 0; s < S_1; s++) {
            int o = (n * S_1 + s) * D + d;
            float a = g_pm1_1[o], bb = g_pm2_1[o];
            if (a > m1) { m2 = fmaxf(m1, bb); m1 = a; idx = g_pix_1[o]; }
            else        { m2 = fmaxf(m2, a); }
        }
        sm1[d] = m1;
        g_c1[n * D + d] = m2 - m1;
        g_am1[n * D + d] = idx;
    }
    __syncthreads();

    // base_g[n,o] = b_g[o] + sum_d m1_x0 * W_g[o,128+d] + sum_d m1_x1 * W_g[o,256+d]
    // float4 loads (16B granularity on the stride-H pattern) + 8 accumulators.
    {
        const float* w; const float* bb; float* out; int o;
        if (t < D) { o = t;       w = W0 + (size_t)o * H; bb = b0; out = g_base0; }
        else       { o = t - D;   w = W1 + (size_t)o * H; bb = b1; out = g_base1; }
        const float4* wA = (const float4*)(w + 128);
        const float4* wB = (const float4*)(w + 256);
        const float4* s0 = (const float4*)sm0;
        const float4* s1v = (const float4*)sm1;
        float a0 = bb[o], a1 = 0.f, a2 = 0.f, a3 = 0.f;
        float c0 = 0.f, c1 = 0.f, c2 = 0.f, c3 = 0.f;
#pragma unroll 8
        for (int j = 0; j < D / 4; j++) {
            float4 wa = wA[j], sa = s0[j];
            a0 += sa.x * wa.x; a1 += sa.y * wa.y; a2 += sa.z * wa.z; a3 += sa.w * wa.w;
            float4 wb = wB[j], sb = s1v[j];
            c0 += sb.x * wb.x; c1 += sb.y * wb.y; c2 += sb.z * wb.z; c3 += sb.w * wb.w;
        }
        out[n * D + o] = ((a0 + a1) + (a2 + a3)) + ((c0 + c1) + (c2 + c3));
    }
}

// ---------------- K3: both GEMMs in ONE launch -------------------------------
// y = x @ Wa^T + base + sparse LOO corrections.
// Block: 256 threads, tile TM=64 rows x 128 cols, K=128 in 8 chunks of 16,
// double-buffered smem with register staging (one __syncthreads per chunk).
// Thread (tx,ty): 8 rows (ty*8..+7) x 4 cols (tx*4..+3), packed f32x2 row-pairs.
// __launch_bounds__(256, 2): force >=2 blocks/SM (caps regs at 128; est. usage
// ~104 so no spills expected). Tests H1 (round-6 was 1 block/SM). If the bench
// lands >45us gemm with this in place, H2 (FFMA2 half-rate) is confirmed and
// the next move is tcgen05 tf32 hi/lo.
__global__ void __launch_bounds__(256, 2) k_gemm_all(
        const float* __restrict__ x0, const float* __restrict__ W0,
        const float* __restrict__ x1, const float* __restrict__ W1,
        float* __restrict__ y0, float* __restrict__ y1) {
    __shared__ __align__(16) float xs[2][KC][TM + 4];   // 2*16*68*4  = 8704 B
    __shared__ __align__(16) float ws[2][KC][D + 4];    // 2*16*132*4 = 16896 B
    __shared__ __align__(16) float sB[D];
    __shared__ float sC[D];
    __shared__ int   sAm[D];

    // ---- group select (block-uniform) ----
    const float *x, *W; float* y;
    const float* gC; const float* gB; const int* gAm;
    int L, OFF, n, l0;
    if (blockIdx.x < GEMM_BLKS_0) {
        x = x0; W = W0; y = y0; L = L_0; OFF = 128;
        gC = g_c0; gB = g_base0; gAm = g_am0;
        n  = blockIdx.x / (L_0 / TM);
        l0 = (blockIdx.x % (L_0 / TM)) * TM;
    } else {
        int bid = blockIdx.x - GEMM_BLKS_0;
        x = x1; W = W1; y = y1; L = L_1; OFF = 256;
        gC = g_c1; gB = g_base1; gAm = g_am1;
        n  = bid / (L_1 / TM);
        l0 = (bid % (L_1 / TM)) * TM;
    }
    const float* xblk = x + ((size_t)n * L + l0) * D;

    const int t  = threadIdx.x;
    const int tx = t & 31;    // col quad
    const int ty = t >> 5;    // row octet (== warp id)

    if (t < D) {
        sC[t] = gC[n * D + t]; sAm[t] = gAm[n * D + t]; sB[t] = gB[n * D + t];
    }

    // staging registers: 1 float4 of x, 2 float4 of W per thread per chunk
    const int xrow = t >> 2, xcq = t & 3;           // 64 rows x 4 col-quads
    const int wo0 = t >> 2,        wkq0 = t & 3;    // first 256 float4s of W chunk
    const int wo1 = (t + 256) >> 2, wkq1 = t & 3;   // second 256

    float4 xr, wr0, wr1;
    auto ldR = [&](int kc) {
        xr  = *(const float4*)(xblk + (size_t)xrow * D + kc + xcq * 4);
        wr0 = *(const float4*)(W + (size_t)wo0 * H + kc + wkq0 * 4);
        wr1 = *(const float4*)(W + (size_t)wo1 * H + kc + wkq1 * 4);
    };
    auto stS = [&](int b) {
        xs[b][xcq * 4 + 0][xrow] = xr.x; xs[b][xcq * 4 + 1][xrow] = xr.y;
        xs[b][xcq * 4 + 2][xrow] = xr.z; xs[b][xcq * 4 + 3][xrow] = xr.w;
        ws[b][wkq0 * 4 + 0][wo0] = wr0.x; ws[b][wkq0 * 4 + 1][wo0] = wr0.y;
        ws[b][wkq0 * 4 + 2][wo0] = wr0.z; ws[b][wkq0 * 4 + 3][wo0] = wr0.w;
        ws[b][wkq1 * 4 + 0][wo1] = wr1.x; ws[b][wkq1 * 4 + 1][wo1] = wr1.y;
        ws[b][wkq1 * 4 + 2][wo1] = wr1.z; ws[b][wkq1 * 4 + 3][wo1] = wr1.w;
    };

    unsigned long long acc[4][4];
#pragma unroll
    for (int p = 0; p < 4; p++)
#pragma unroll
        for (int c = 0; c < 4; c++) acc[p][c] = 0ULL;

    // pipeline prologue
    ldR(0);
    stS(0);
    __syncthreads();

    const int NCH = D / KC;   // 8
#pragma unroll 1
    for (int i = 0; i < NCH; i++) {
        const int b = i & 1;
        if (i + 1 < NCH) ldR((i + 1) * KC);   // LDG overlapped with compute below

#pragma unroll
        for (int k = 0; k < KC; k++) {
            const ulonglong2 xA = *(const ulonglong2*)&xs[b][k][ty * 8];
            const ulonglong2 xB = *(const ulonglong2*)&xs[b][k][ty * 8 + 4];
            const float4 wv = *(const float4*)&ws[b][k][tx * 4];
            const unsigned long long w0 = packdup(wv.x), w1 = packdup(wv.y);
            const unsigned long long w2 = packdup(wv.z), w3 = packdup(wv.w);
            fma2(acc[0][0], xA.x, w0); fma2(acc[0][1], xA.x, w1);
            fma2(acc[0][2], xA.x, w2); fma2(acc[0][3], xA.x, w3);
            fma2(acc[1][0], xA.y, w0); fma2(acc[1][1], xA.y, w1);
            fma2(acc[1][2], xA.y, w2); fma2(acc[1][3], xA.y, w3);
            fma2(acc[2][0], xB.x, w0); fma2(acc[2][1], xB.x, w1);
            fma2(acc[2][2], xB.x, w2); fma2(acc[2][3], xB.x, w3);
            fma2(acc[3][0], xB.y, w0); fma2(acc[3][1], xB.y, w1);
            fma2(acc[3][2], xB.y, w2); fma2(acc[3][3], xB.y, w3);
        }

        if (i + 1 < NCH) {
            stS(b ^ 1);        // safe: all warps finished reading b^1 at previous sync
            __syncthreads();   // next chunk visible; also guards buffer reuse
        }
    }
    __syncthreads();           // sB/sC/sAm visible for epilogue (and final chunk done)

    // epilogue: unpack, sparse LOO corrections (in registers, deterministic), base, store
    float out[8][4];
#pragma unroll
    for (int p = 0; p < 4; p++)
#pragma unroll
        for (int c = 0; c < 4; c++) unpack2(acc[p][c], out[2 * p][c], out[2 * p + 1][c]);

    const float* Wc = W + OFF;
#pragma unroll 1
    for (int d = 0; d < D; d++) {
        int r = sAm[d] - l0;
        if ((unsigned)r < (unsigned)TM && (r >> 3) == ty) {   // uniform per warp (warp == ty)
            float coeff = sC[d];
            int rr = r & 7;
#pragma unroll
            for (int j = 0; j < 4; j++)
                out[rr][j] += coeff * Wc[(size_t)(tx * 4 + j) * H + d];
        }
    }

    const float4 bv = *(const float4*)&sB[tx * 4];
    float* yb = y + ((size_t)n * L + l0) * D + tx * 4;
#pragma unroll
    for (int r = 0; r < 8; r++) {
        float4 o4;
        o4.x = out[r][0] + bv.x; o4.y = out[r][1] + bv.y;
        o4.z = out[r][2] + bv.z; o4.w = out[r][3] + bv.w;
        *(float4*)(yb + (size_t)(ty * 8 + r) * D) = o4;
    }
}

// ---------------- launch ----------------
extern "C" void kernel_launch(void* const* d_in, const int* in_sizes, int n_in,
                              void* d_out, int out_size) {
    const float* x0 = (const float*)d_in[0];
    const float* x1 = (const float*)d_in[1];
    const float* W0 = (const float*)d_in[2];
    const float* b0 = (const float*)d_in[3];
    const float* W1 = (const float*)d_in[4];
    const float* b1 = (const float*)d_in[5];
    float* y0 = (float*)d_out;
    // y0 has exactly in_sizes[0] elements (D_in == D_out == 128)
    float* y1 = y0 + (size_t)in_sizes[0];

    k_reduce_all<<<RED_BLKS_0 + RED_BLKS_1, 128>>>(x0, x1);
    k_combine<<<N_B, 256>>>(W0, b0, W1, b1);
    k_gemm_all<<<GEMM_BLKS_0 + GEMM_BLKS_1, 256>>>(x0, W0, x1, W1, y0, y1);
}